// round 13
// baseline (speedup 1.0000x reference)
#include <cuda_runtime.h>
#include <cstdint>

#define CN    8192
#define NB    4096
#define NBLK  16
#define NTHR  512
#define BPT   (NB / NTHR)    // 8 buckets per thread
#define PPT   (CN / NTHR)    // 16 pairs per thread (hist/scatter)

// Overwrite-only global state: fully rewritten every call (idempotent),
// so NO cleanup pass and NO atomics on persistent state are needed.
__device__ float4   g_pair[CN / 2];   // (v,e) pairs, 2 per float4, 16B aligned
__device__ unsigned g_flag;           // barrier counter, self-resetting (see below)

// smem layout (bytes)
#define OFF_PAIR  0                     // 8192 float2 = 65536
#define OFF_START 65536                 // 4096 int    = 16384
#define OFF_CUR   (65536 + 16384)       // 4096 int    = 16384 (hist -> cursor)
#define OFF_BS    (65536 + 32768)       // 4096 f32    = 16384 (bsum -> excl-suffix)
#define OFF_W     (65536 + 49152)       // scratch
#define SMEM_BYTES (OFF_W + 256)

__device__ __forceinline__ unsigned atom_add_release(unsigned* p, unsigned a) {
    unsigned old;
    asm volatile("atom.release.gpu.global.add.u32 %0, [%1], %2;"
                 : "=r"(old) : "l"(p), "r"(a) : "memory");
    return old;
}
__device__ __forceinline__ unsigned ld_acquire(const unsigned* p) {
    unsigned v;
    asm volatile("ld.acquire.gpu.global.u32 %0, [%1];"
                 : "=r"(v) : "l"(p) : "memory");
    return v;
}
__device__ __forceinline__ void fence_acqrel_gpu() {
    asm volatile("fence.acq_rel.gpu;" ::: "memory");
}

// Monotone bucket map: b_j > b_i => sv_j > sv_i ; b_j < b_i => sv_j < sv_i.
__device__ __forceinline__ int bkt(float v) {
    float x = v * (float)NB;
    x = fminf(fmaxf(x, 0.0f), (float)(NB - 1));
    return (int)x;
}

__global__ void __launch_bounds__(NTHR) cox_local(
    const float* __restrict__ theta,
    const float* __restrict__ sv,
    const float* __restrict__ cen,
    float* __restrict__ out)
{
    extern __shared__ char sm[];
    float2* s_pair  = (float2*)(sm + OFF_PAIR);
    int*    s_start = (int*)   (sm + OFF_START);
    int*    s_cur   = (int*)   (sm + OFF_CUR);
    float*  s_bs    = (float*) (sm + OFF_BS);
    float*  s_w     = (float*) (sm + OFF_W);

    const int t    = threadIdx.x;
    const int lane = t & 31;
    const int wid  = t >> 5;
    const int gid  = blockIdx.x * NTHR + t;       // own element, 0..8191

    // ---- Phase A: own element -> exp -> overwrite g_pair[gid] (no atomics) --
    const float v  = sv[gid];
    const float th = theta[gid];
    const float ce = cen[gid];
    const float e  = __expf(th);
    reinterpret_cast<float2*>(g_pair)[gid] = make_float2(v, e);
    if (gid == 0) out[0] = 0.0f;

    // zero smem hist while phase-A stores drain
    #pragma unroll
    for (int i = 0; i < BPT; i++) {
        s_cur[t + i * NTHR] = 0;
        s_bs [t + i * NTHR] = 0.0f;
    }

    // ---- self-resetting global barrier (release/acquire, double-count) ----
    __syncthreads();                              // all block stores issued
    if (t == 0) {
        atom_add_release(&g_flag, 1u);            // arrive (release own stores)
        while (ld_acquire(&g_flag) < NBLK) { }    // wait for all arrivals
        // second count: values stay >= NBLK for spinners; the 2*NBLK-th add
        // proves every block has passed the spin -> safe to reset to 0.
        unsigned o2 = atomicAdd(&g_flag, 1u);
        if (o2 == 2u * NBLK - 1u) {
            asm volatile("st.relaxed.gpu.global.u32 [%0], %1;"
                         :: "l"(&g_flag), "r"(0u) : "memory");
        }
    }
    __syncthreads();
    fence_acqrel_gpu();                           // propagate acquire to all threads

    // ---- bulk load ALL pairs (one L2 pass, full MLP) + smem histogram ----
    float4 pr[PPT / 2];                           // 8 float4 = 16 pairs
    #pragma unroll
    for (int k = 0; k < PPT / 2; k++)
        pr[k] = g_pair[k * NTHR + t];
    #pragma unroll
    for (int k = 0; k < PPT / 2; k++) {
        int b0 = bkt(pr[k].x);
        atomicAdd(&s_cur[b0], 1);
        atomicAdd(&s_bs [b0], pr[k].y);
        int b1 = bkt(pr[k].z);
        atomicAdd(&s_cur[b1], 1);
        atomicAdd(&s_bs [b1], pr[k].w);
    }
    __syncthreads();

    // ---- forward exclusive scan of counts -> s_start, reset s_cur=start ----
    {
        int c[BPT], tsum = 0;
        #pragma unroll
        for (int i = 0; i < BPT; i++) { c[i] = s_cur[t * BPT + i]; tsum += c[i]; }
        int val = tsum;
        #pragma unroll
        for (int o = 1; o < 32; o <<= 1) {
            int n = __shfl_up_sync(0xffffffffu, val, o);
            if (lane >= o) val += n;
        }
        if (lane == 31) ((int*)s_w)[wid] = val;
        __syncthreads();
        if (t < 16) {
            int wv = ((int*)s_w)[t];
            #pragma unroll
            for (int o = 1; o < 16; o <<= 1) {
                int n = __shfl_up_sync(0x0000ffffu, wv, o);
                if (t >= o) wv += n;
            }
            ((int*)s_w)[t] = wv;
        }
        __syncthreads();
        int base = val - tsum + ((wid > 0) ? ((int*)s_w)[wid - 1] : 0);
        #pragma unroll
        for (int i = 0; i < BPT; i++) {
            s_start[t * BPT + i] = base;
            s_cur  [t * BPT + i] = base;          // scatter cursor
            base += c[i];
        }
    }
    __syncthreads();

    // ---- suffix scan of bucket sums -> s_bs becomes EXCLUSIVE suffix ----
    {
        const int c = (NTHR - 1) - t;             // chunk, reversed order
        float g[BPT];
        float gs = 0.0f;
        #pragma unroll
        for (int i = 0; i < BPT; i++) { g[i] = s_bs[c * BPT + i]; gs += g[i]; }
        float val = gs;                           // inclusive over t asc = suffix
        #pragma unroll
        for (int o = 1; o < 32; o <<= 1) {
            float n = __shfl_up_sync(0xffffffffu, val, o);
            if (lane >= o) val += n;
        }
        if (lane == 31) s_w[wid] = val;
        __syncthreads();
        if (t < 16) {
            float wv = s_w[t];
            #pragma unroll
            for (int o = 1; o < 16; o <<= 1) {
                float n = __shfl_up_sync(0x0000ffffu, wv, o);
                if (t >= o) wv += n;
            }
            s_w[t] = wv;
        }
        __syncthreads();
        val += (wid > 0) ? s_w[wid - 1] : 0.0f;   // suffix INCLUDING own chunk
        float run = val - gs;                     // suffix of later chunks
        #pragma unroll
        for (int i = BPT - 1; i >= 0; i--) {
            s_bs[c * BPT + i] = run;              // EXCLUSIVE suffix for bucket
            run += g[i];
        }
    }
    __syncthreads();

    // ---- counting-sort scatter into s_pair ----
    #pragma unroll
    for (int k = 0; k < PPT / 2; k++) {
        int b0 = bkt(pr[k].x);
        int p0 = atomicAdd(&s_cur[b0], 1);
        s_pair[p0] = make_float2(pr[k].x, pr[k].y);
        int b1 = bkt(pr[k].z);
        int p1 = atomicAdd(&s_cur[b1], 1);
        s_pair[p1] = make_float2(pr[k].z, pr[k].w);
    }
    __syncthreads();

    // ---- own row: exact within-bucket + exclusive bucket suffix ----
    const int b   = bkt(v);
    const int lo  = s_start[b];
    const int hi  = s_cur[b];                     // start + count (post-scatter)
    float w = 0.0f;
    for (int m = lo; m < hi; m++) {               // avg 2 iterations (incl self)
        float2 s = s_pair[m];
        if (s.x >= v) w += s.y;
    }
    float risk = s_bs[b] + w;
    float acc  = (th - __logf(risk)) * ce;

    // ---- block reduce + single atomic into out ----
    #pragma unroll
    for (int o = 16; o > 0; o >>= 1) acc += __shfl_xor_sync(0xffffffffu, acc, o);
    if (lane == 0) s_w[wid] = acc;
    __syncthreads();
    if (t == 0) {
        float ps = 0.0f;
        #pragma unroll
        for (int q = 0; q < NTHR / 32; q++) ps += s_w[q];
        atomicAdd(out, -ps / (float)CN);          // final value with last block's add
    }
}

extern "C" void kernel_launch(void* const* d_in, const int* in_sizes, int n_in,
                              void* d_out, int out_size) {
    const float* hazard_pred = (const float*)d_in[0];
    const float* survtime    = (const float*)d_in[1];
    const float* censor      = (const float*)d_in[2];
    float* out = (float*)d_out;

    cudaFuncSetAttribute(cox_local,
                         cudaFuncAttributeMaxDynamicSharedMemorySize, SMEM_BYTES);
    cox_local<<<NBLK, NTHR, SMEM_BYTES>>>(hazard_pred, survtime, censor, out);
}